// round 1
// baseline (speedup 1.0000x reference)
#include <cuda_runtime.h>
#include <cstdint>

#define DEV __device__ __forceinline__

// ---------------- problem constants ----------------
constexpr int NN   = 10000;
constexpr int FIN  = 512;
constexpr int HID  = 256;
constexpr int NCLS = 64;

// ---------------- scratch (no allocations allowed) ----------------
static __device__ float g_S1[NN * HID];    // feature @ W1
static __device__ float g_S2[NN * NCLS];   // X1 @ W2
static __device__ float g_X2[NN * NCLS];   // adj @ S2 + b2

// ---------------- helpers ----------------
DEV uint32_t f2tf(float f) {
    uint32_t u;
    asm("cvt.rna.tf32.f32 %0, %1;" : "=r"(u) : "f"(f));
    return u;
}

DEV void cp16(void* smem, const void* gmem) {
    uint32_t s = (uint32_t)__cvta_generic_to_shared(smem);
    asm volatile("cp.async.cg.shared.global [%0], [%1], 16;" :: "r"(s), "l"(gmem));
}
DEV void cp_commit() { asm volatile("cp.async.commit_group;"); }
template <int NG> DEV void cp_wait() { asm volatile("cp.async.wait_group %0;" :: "n"(NG)); }

DEV void mma8(float* c, const uint32_t* a, const uint32_t* b) {
    asm volatile(
        "mma.sync.aligned.m16n8k8.row.col.f32.tf32.tf32.f32 "
        "{%0,%1,%2,%3},{%4,%5,%6,%7},{%8,%9},{%0,%1,%2,%3};"
        : "+f"(c[0]), "+f"(c[1]), "+f"(c[2]), "+f"(c[3])
        : "r"(a[0]), "r"(a[1]), "r"(a[2]), "r"(a[3]), "r"(b[0]), "r"(b[1]));
}

// ---------------- TF32 GEMM ----------------
// C[M,N] = A[M,K] @ B[K,N] (+bias) (+relu)
// EPI: 0 = plain, 1 = +bias, relu, 2 = +bias
// Block tile 128x128x16, 256 threads (8 warps as 4(M) x 2(N), warp tile 32x64).
constexpr int BM = 128, BN = 128, BK = 16;
constexpr int AS_STRIDE = 20;   // conflict-free A fragment reads (20 mod 32 pattern)
constexpr int BS_STRIDE = 136;  // stride mod 32 == 8 -> conflict-free B fragment reads

template <int EPI>
__global__ __launch_bounds__(256)
void gemm_tf32(const float* __restrict__ A, const float* __restrict__ B,
               const float* __restrict__ bias, float* __restrict__ C,
               int M, int N, int K) {
    __shared__ __align__(16) float As[2][BM * AS_STRIDE];
    __shared__ __align__(16) float Bs[2][BK * BS_STRIDE];

    const int tid = threadIdx.x;
    const int bm = blockIdx.y * BM;
    const int bn = blockIdx.x * BN;

    // global->smem mapping
    const int ar = tid >> 2;          // 0..63  (A row within tile, +64 for 2nd)
    const int ac = (tid & 3) * 4;     // 0,4,8,12
    const int br = tid >> 5;          // 0..7   (B k-row within tile, +8 for 2nd)
    const int bc = (tid & 31) * 4;    // 0..124

    auto load_tiles = [&](int buf, int kk) {
        #pragma unroll
        for (int i = 0; i < 2; ++i) {
            int r = ar + i * 64;
            float* dst = &As[buf][r * AS_STRIDE + ac];
            int grow = bm + r;
            if (grow < M) cp16(dst, &A[(long long)grow * K + kk + ac]);
            else *reinterpret_cast<float4*>(dst) = make_float4(0.f, 0.f, 0.f, 0.f);
        }
        #pragma unroll
        for (int i = 0; i < 2; ++i) {
            int r = br + i * 8;
            float* dst = &Bs[buf][r * BS_STRIDE + bc];
            int gcol = bn + bc;
            if (gcol < N) cp16(dst, &B[(long long)(kk + r) * N + gcol]);
            else *reinterpret_cast<float4*>(dst) = make_float4(0.f, 0.f, 0.f, 0.f);
        }
    };

    const int warp = tid >> 5;
    const int lane = tid & 31;
    const int wm = warp & 3;     // 0..3 -> rows wm*32
    const int wn = warp >> 2;    // 0..1 -> cols wn*64
    const int g = lane >> 2;     // groupID
    const int tig = lane & 3;    // threadID_in_group

    float acc[2][8][4];
    #pragma unroll
    for (int i = 0; i < 2; ++i)
        #pragma unroll
        for (int j = 0; j < 8; ++j)
            #pragma unroll
            for (int k = 0; k < 4; ++k) acc[i][j][k] = 0.f;

    const int KT = K / BK;
    load_tiles(0, 0);
    cp_commit();

    for (int kt = 0; kt < KT; ++kt) {
        const int buf = kt & 1;
        if (kt + 1 < KT) {
            load_tiles(buf ^ 1, (kt + 1) * BK);
            cp_commit();
            cp_wait<1>();
        } else {
            cp_wait<0>();
        }
        __syncthreads();

        #pragma unroll
        for (int ks = 0; ks < BK; ks += 8) {
            const float* Ab = &As[buf][0];
            const float* Bb = &Bs[buf][0];
            uint32_t a[2][4];
            #pragma unroll
            for (int mf = 0; mf < 2; ++mf) {
                int rb = wm * 32 + mf * 16 + g;
                a[mf][0] = f2tf(Ab[(rb)     * AS_STRIDE + ks + tig]);
                a[mf][1] = f2tf(Ab[(rb + 8) * AS_STRIDE + ks + tig]);
                a[mf][2] = f2tf(Ab[(rb)     * AS_STRIDE + ks + tig + 4]);
                a[mf][3] = f2tf(Ab[(rb + 8) * AS_STRIDE + ks + tig + 4]);
            }
            uint32_t b[8][2];
            #pragma unroll
            for (int nf = 0; nf < 8; ++nf) {
                int cb = wn * 64 + nf * 8 + g;
                b[nf][0] = f2tf(Bb[(ks + tig)     * BS_STRIDE + cb]);
                b[nf][1] = f2tf(Bb[(ks + tig + 4) * BS_STRIDE + cb]);
            }
            #pragma unroll
            for (int mf = 0; mf < 2; ++mf)
                #pragma unroll
                for (int nf = 0; nf < 8; ++nf)
                    mma8(acc[mf][nf], a[mf], b[nf]);
        }
        __syncthreads();
    }

    // epilogue: C layout c0,c1 -> (row g, cols 2t,2t+1); c2,c3 -> (row g+8)
    #pragma unroll
    for (int mf = 0; mf < 2; ++mf) {
        #pragma unroll
        for (int nf = 0; nf < 8; ++nf) {
            int c = bn + wn * 64 + nf * 8 + 2 * tig;
            if (c >= N) continue;
            float bv0 = 0.f, bv1 = 0.f;
            if (EPI != 0) { bv0 = bias[c]; bv1 = bias[c + 1]; }
            #pragma unroll
            for (int h = 0; h < 2; ++h) {
                int r = bm + wm * 32 + mf * 16 + g + h * 8;
                if (r >= M) continue;
                float v0 = acc[mf][nf][2 * h]     + bv0;
                float v1 = acc[mf][nf][2 * h + 1] + bv1;
                if (EPI == 1) { v0 = fmaxf(v0, 0.f); v1 = fmaxf(v1, 0.f); }
                *reinterpret_cast<float2*>(&C[(long long)r * N + c]) = make_float2(v0, v1);
            }
        }
    }
}

// ---------------- log-softmax over rows of 64 ----------------
__global__ void logsoftmax64(const float* __restrict__ X, float* __restrict__ out, int M) {
    int w = (int)((blockIdx.x * blockDim.x + threadIdx.x) >> 5);
    int lane = threadIdx.x & 31;
    if (w >= M) return;
    const float* x = X + (long long)w * 64;
    float v0 = x[lane], v1 = x[lane + 32];
    float m = fmaxf(v0, v1);
    #pragma unroll
    for (int o = 16; o > 0; o >>= 1) m = fmaxf(m, __shfl_xor_sync(0xffffffffu, m, o));
    float s = expf(v0 - m) + expf(v1 - m);
    #pragma unroll
    for (int o = 16; o > 0; o >>= 1) s += __shfl_xor_sync(0xffffffffu, s, o);
    float l = m + logf(s);
    float* o64 = out + (long long)w * 64;
    o64[lane]      = v0 - l;
    o64[lane + 32] = v1 - l;
}

// ---------------- launch ----------------
extern "C" void kernel_launch(void* const* d_in, const int* in_sizes, int n_in,
                              void* d_out, int out_size) {
    const float* feature = (const float*)d_in[0];   // [10000, 512]
    const float* adj     = (const float*)d_in[1];   // [10000, 10000]
    const float* W1      = (const float*)d_in[2];   // [512, 256]
    const float* b1      = (const float*)d_in[3];   // [256]
    const float* W2      = (const float*)d_in[4];   // [256, 64]
    const float* b2      = (const float*)d_in[5];   // [64]

    float* out = (float*)d_out;
    float* x1  = out;                               // [10000, 256]
    float* lsm = out + (long long)NN * HID;         // [10000, 64]

    float *S1p, *S2p, *X2p;
    cudaGetSymbolAddress((void**)&S1p, g_S1);
    cudaGetSymbolAddress((void**)&S2p, g_S2);
    cudaGetSymbolAddress((void**)&X2p, g_X2);

    const dim3 blk(256);
    const int mt = (NN + BM - 1) / BM;  // 79

    // S1 = feature @ W1
    gemm_tf32<0><<<dim3(HID / BN, mt), blk>>>(feature, W1, nullptr, S1p, NN, HID, FIN);
    // X1 = relu(adj @ S1 + b1)  -> written directly into d_out
    gemm_tf32<1><<<dim3(HID / BN, mt), blk>>>(adj, S1p, b1, x1, NN, HID, NN);
    // S2 = X1 @ W2
    gemm_tf32<0><<<dim3(1, mt), blk>>>(x1, W2, nullptr, S2p, NN, NCLS, HID);
    // X2 = adj @ S2 + b2
    gemm_tf32<2><<<dim3(1, mt), blk>>>(adj, S2p, b2, X2p, NN, NCLS, NN);
    // log_softmax rows
    logsoftmax64<<<(NN * 32 + 255) / 256, blk>>>(X2p, lsm, NN);
}

// round 3
// speedup vs baseline: 1.5450x; 1.5450x over previous
#include <cuda_runtime.h>
#include <cstdint>

#define DEV __device__ __forceinline__

// ---------------- problem constants ----------------
constexpr int NN   = 10000;
constexpr int FIN  = 512;
constexpr int HID  = 256;
constexpr int NCLS = 64;

// ---------------- scratch ----------------
static __device__ float g_S1p[NN * HID];     // S1 = feature@W1, column-permuted (pi128), rna
static __device__ float g_S2p[NN * NCLS];    // S2 = X1@W2, column-permuted (pi64), rna
static __device__ float g_W1p[FIN * HID];    // W1 permuted (pi128 per 128-col block), rna
static __device__ float g_W2p[HID * NCLS];   // W2 permuted (pi64), rna
static __device__ float g_part[2 * NN * NCLS]; // split-K partials of adj@S2

// ---------------- helpers ----------------
DEV float rna(float x) {
    uint32_t u;
    asm("cvt.rna.tf32.f32 %0, %1;" : "=r"(u) : "f"(x));
    return __uint_as_float(u);
}

DEV void cp16z(void* smem, const void* gmem, int sz) {
    uint32_t s = (uint32_t)__cvta_generic_to_shared(smem);
    asm volatile("cp.async.cg.shared.global [%0], [%1], 16, %2;" :: "r"(s), "l"(gmem), "r"(sz));
}
DEV void cp_commit() { asm volatile("cp.async.commit_group;"); }
template <int NG> DEV void cp_wait() { asm volatile("cp.async.wait_group %0;" :: "n"(NG)); }

// m16n8k8 tf32 mma; operands are raw fp32 bits (HW truncates to tf32)
DEV void mma8(float* c, const float* a, float b0f, float b1f) {
    uint32_t a0 = __float_as_uint(a[0]), a1 = __float_as_uint(a[1]);
    uint32_t a2 = __float_as_uint(a[2]), a3 = __float_as_uint(a[3]);
    uint32_t b0 = __float_as_uint(b0f), b1 = __float_as_uint(b1f);
    asm volatile(
        "mma.sync.aligned.m16n8k8.row.col.f32.tf32.tf32.f32 "
        "{%0,%1,%2,%3},{%4,%5,%6,%7},{%8,%9},{%0,%1,%2,%3};"
        : "+f"(c[0]), "+f"(c[1]), "+f"(c[2]), "+f"(c[3])
        : "r"(a0), "r"(a1), "r"(a2), "r"(a3), "r"(b0), "r"(b1));
}

// ============================================================================
// TF32 mma.sync GEMM:  C[M,N] = A[M,K] @ B[K,N]  (B pre-permuted per BN block)
// BM=64 fixed, 128 threads, 4 warps as 2(M) x 2(N). BK=16 per stage.
//   BN=128 -> WN=64 (warp 32x64) ; BN=64 -> WN=32 (warp 32x32)
// B smem layout: row k, col pi(n): pi(n) = (n&7)*(BN/8) + (n>>3) within block.
// EPI: 0 raw ; 1 bias+relu+rna ; 3 rna.   PERM: 0 plain store ; else pi store.
// Split-K via blockIdx.z: C += z*M*N, k range [z*kh, z*kh+ksz).
// ============================================================================
template <int BN, int WN, int STAGES, int EPI, int PERM>
__global__ __launch_bounds__(128)
void gemm_mma(const float* __restrict__ A, const float* __restrict__ B,
              const float* __restrict__ bias, float* __restrict__ C,
              int M, int N, int K)
{
    constexpr int BM = 64, BK = 16;
    constexpr int ASTRIDE = 20;            // floats per A smem row (conflict-free)
    constexpr int BSTRIDE = BN + 4;        // 132 / 68 floats per B smem k-row
    constexpr int AWORDS = BM * ASTRIDE;   // 1280
    constexpr int SW = AWORDS + BK * BSTRIDE;  // words per stage

    extern __shared__ float sm[];

    const int tid  = threadIdx.x;
    const int warp = tid >> 5;
    const int lane = tid & 31;
    const int wm = warp & 1;           // 0..1 -> rows wm*32
    const int wn = warp >> 1;          // 0..1 -> cols wn*WN
    const int g = lane >> 2;           // groupID 0..7
    const int tig = lane & 3;          // thread in group

    const int bm = blockIdx.y * BM;
    const int bn = blockIdx.x * BN;

    // split-K range
    const int z  = blockIdx.z;
    const int kh = (gridDim.z == 1) ? K : (((K / gridDim.z) + 15) & ~15);
    const int k0 = z * kh;
    const int ksz = (K - k0 < kh) ? (K - k0) : kh;
    float* Cz = C + (long long)z * M * N;

    // ---- loaders ----
    auto load_stage = [&](int stg, int kk) {
        float* As = sm + stg * SW;
        float* Bs = As + AWORDS;
        // A: 64 rows x 4 chunks of 16B
        const int ar = tid >> 2;       // 0..31
        const int ac = (tid & 3) * 4;
        #pragma unroll
        for (int i = 0; i < 2; ++i) {
            int r = ar + i * 32;
            int grow = bm + r;
            int sz = (grow < M) ? 16 : 0;
            const float* src = A + (long long)((grow < M) ? grow : 0) * K + k0 + kk + ac;
            cp16z(As + r * ASTRIDE + ac, src, sz);
        }
        // B: 16 k-rows x BN floats
        if (BN == 128) {
            const int br = tid >> 5;       // 0..3
            const int bc = (tid & 31) * 4;
            #pragma unroll
            for (int j = 0; j < 4; ++j) {
                int kr = br + j * 4;
                const float* src = B + (long long)(k0 + kk + kr) * N + bn + bc;
                cp16z(Bs + kr * BSTRIDE + bc, src, 16);
            }
        } else {
            const int br = tid >> 4;       // 0..7
            const int bc = (tid & 15) * 4;
            #pragma unroll
            for (int j = 0; j < 2; ++j) {
                int kr = br + j * 8;
                const float* src = B + (long long)(k0 + kk + kr) * N + bn + bc;
                cp16z(Bs + kr * BSTRIDE + bc, src, 16);
            }
        }
        cp_commit();
    };

    float acc[2][WN / 8][4];
    #pragma unroll
    for (int i = 0; i < 2; ++i)
        #pragma unroll
        for (int j = 0; j < WN / 8; ++j)
            #pragma unroll
            for (int k = 0; k < 4; ++k) acc[i][j][k] = 0.f;

    const int goff = g * (BN / 8) + wn * (WN / 8);

    auto compute_stage = [&](int stg) {
        const float* As = sm + stg * SW;
        const float* Bs = As + AWORDS;
        #pragma unroll
        for (int ks = 0; ks < BK; ks += 8) {
            float a[2][4];
            #pragma unroll
            for (int mf = 0; mf < 2; ++mf) {
                const float* ap = As + (wm * 32 + mf * 16 + g) * ASTRIDE + ks + tig;
                a[mf][0] = ap[0];
                a[mf][1] = ap[8 * ASTRIDE];
                a[mf][2] = ap[4];
                a[mf][3] = ap[8 * ASTRIDE + 4];
            }
            const float* bp0 = Bs + (ks + tig) * BSTRIDE + goff;
            const float* bp1 = bp0 + 4 * BSTRIDE;
            float4 bl0 = *reinterpret_cast<const float4*>(bp0);
            float4 bl1 = *reinterpret_cast<const float4*>(bp1);
            #pragma unroll
            for (int mf = 0; mf < 2; ++mf) {
                mma8(acc[mf][0], a[mf], bl0.x, bl1.x);
                mma8(acc[mf][1], a[mf], bl0.y, bl1.y);
                mma8(acc[mf][2], a[mf], bl0.z, bl1.z);
                mma8(acc[mf][3], a[mf], bl0.w, bl1.w);
            }
            if (WN == 64) {
                float4 bh0 = *reinterpret_cast<const float4*>(bp0 + 4);
                float4 bh1 = *reinterpret_cast<const float4*>(bp1 + 4);
                #pragma unroll
                for (int mf = 0; mf < 2; ++mf) {
                    mma8(acc[mf][4], a[mf], bh0.x, bh1.x);
                    mma8(acc[mf][5], a[mf], bh0.y, bh1.y);
                    mma8(acc[mf][6], a[mf], bh0.z, bh1.z);
                    mma8(acc[mf][7], a[mf], bh0.w, bh1.w);
                }
            }
        }
    };

    // ---- multistage pipeline ----
    const int KT = ksz / BK;
    #pragma unroll
    for (int s = 0; s < STAGES - 1; ++s) load_stage(s, s * BK);

    for (int kt = 0; kt < KT; ++kt) {
        cp_wait<STAGES - 2>();
        __syncthreads();
        const int nk = kt + STAGES - 1;
        if (nk < KT) load_stage(nk % STAGES, nk * BK);
        else cp_commit();   // keep group accounting so wait<S-2> drains the tail
        compute_stage(kt % STAGES);
    }

    // ---- epilogue ----
    #pragma unroll
    for (int mf = 0; mf < 2; ++mf) {
        #pragma unroll
        for (int nf = 0; nf < WN / 8; ++nf) {
            const int l = wn * WN + nf * 8 + 2 * tig;   // local col (even)
            const int c = bn + l;
            float bv0 = 0.f, bv1 = 0.f;
            if (EPI == 1) { bv0 = bias[c]; bv1 = bias[c + 1]; }
            #pragma unroll
            for (int h = 0; h < 2; ++h) {
                const int r = bm + wm * 32 + mf * 16 + g + h * 8;
                if (r >= M) continue;
                float v0 = acc[mf][nf][2 * h];
                float v1 = acc[mf][nf][2 * h + 1];
                if (EPI == 1) {
                    v0 = fmaxf(v0 + bv0, 0.f);
                    v1 = fmaxf(v1 + bv1, 0.f);
                }
                if (EPI == 1 || EPI == 3) { v0 = rna(v0); v1 = rna(v1); }
                if (PERM == 0) {
                    *reinterpret_cast<float2*>(&Cz[(long long)r * N + c]) = make_float2(v0, v1);
                } else {
                    const int p = (l & 7) * (PERM / 8) + (l >> 3);
                    Cz[(long long)r * N + bn + p] = v0;
                    Cz[(long long)r * N + bn + p + PERM / 8] = v1;
                }
            }
        }
    }
}

// ---------------- weight permute (+rna): out[r][cb + pi(cl)] = rna(in[r][c]) --
template <int BLK>
__global__ void permW(const float* __restrict__ in, float* __restrict__ out, int R, int C) {
    int i = blockIdx.x * blockDim.x + threadIdx.x;
    if (i < R * C) {
        int c = i % C;
        int cl = c & (BLK - 1);
        int cb = c - cl;
        int p = (cl & 7) * (BLK / 8) + (cl >> 3);
        out[(i - c) + cb + p] = rna(in[i]);
    }
}

// ---------------- combine split-K partials + bias + log-softmax -------------
__global__ void lsm_combine(const float* __restrict__ p0, const float* __restrict__ p1,
                            const float* __restrict__ b2, float* __restrict__ out, int M) {
    int w = (int)((blockIdx.x * blockDim.x + threadIdx.x) >> 5);
    int lane = threadIdx.x & 31;
    if (w >= M) return;
    long long base = (long long)w * 64;
    float x0 = p0[base + lane]      + p1[base + lane]      + b2[lane];
    float x1 = p0[base + lane + 32] + p1[base + lane + 32] + b2[lane + 32];
    float m = fmaxf(x0, x1);
    #pragma unroll
    for (int o = 16; o > 0; o >>= 1) m = fmaxf(m, __shfl_xor_sync(0xffffffffu, m, o));
    float s = expf(x0 - m) + expf(x1 - m);
    #pragma unroll
    for (int o = 16; o > 0; o >>= 1) s += __shfl_xor_sync(0xffffffffu, s, o);
    float l = m + logf(s);
    out[base + lane]      = x0 - l;
    out[base + lane + 32] = x1 - l;
}

// ---------------- launch ----------------
extern "C" void kernel_launch(void* const* d_in, const int* in_sizes, int n_in,
                              void* d_out, int out_size) {
    const float* feature = (const float*)d_in[0];   // [10000, 512]
    const float* adj     = (const float*)d_in[1];   // [10000, 10000]
    const float* W1      = (const float*)d_in[2];   // [512, 256]
    const float* b1      = (const float*)d_in[3];   // [256]
    const float* W2      = (const float*)d_in[4];   // [256, 64]
    const float* b2      = (const float*)d_in[5];   // [64]

    float* out = (float*)d_out;
    float* x1  = out;                               // [10000, 256]
    float* lsm = out + (long long)NN * HID;         // [10000, 64]

    float *S1p, *S2p, *W1p, *W2p, *part;
    cudaGetSymbolAddress((void**)&S1p, g_S1p);
    cudaGetSymbolAddress((void**)&S2p, g_S2p);
    cudaGetSymbolAddress((void**)&W1p, g_W1p);
    cudaGetSymbolAddress((void**)&W2p, g_W2p);
    cudaGetSymbolAddress((void**)&part, g_part);

    // gemm instantiations:            BN   WN  ST EPI PERM
    auto* G0 = gemm_mma<128, 64, 5, 3, 128>;
    auto* G1 = gemm_mma<128, 64, 5, 1, 0>;
    auto* G2 = gemm_mma<64,  32, 5, 3, 64>;
    auto* G3 = gemm_mma<64,  32, 6, 0, 0>;

    constexpr int SW128 = (64 * 20 + 16 * 132) * 4;   // 13568 B/stage
    constexpr int SW64  = (64 * 20 + 16 * 68) * 4;    // 9472 B/stage
    constexpr int SM_G01 = 5 * SW128;                 // 67840
    constexpr int SM_G2  = 5 * SW64;                  // 47360
    constexpr int SM_G3  = 6 * SW64;                  // 56832

    cudaFuncSetAttribute(G0, cudaFuncAttributeMaxDynamicSharedMemorySize, SM_G01);
    cudaFuncSetAttribute(G1, cudaFuncAttributeMaxDynamicSharedMemorySize, SM_G01);
    cudaFuncSetAttribute(G2, cudaFuncAttributeMaxDynamicSharedMemorySize, SM_G2);
    cudaFuncSetAttribute(G3, cudaFuncAttributeMaxDynamicSharedMemorySize, SM_G3);

    const int MT = (NN + 63) / 64;   // 157

    // weight permutes (tiny)
    permW<128><<<(FIN * HID + 255) / 256, 256>>>(W1, W1p, FIN, HID);
    permW<64><<<(HID * NCLS + 255) / 256, 256>>>(W2, W2p, HID, NCLS);

    // G0: S1p = pi128(rna(feature @ W1p))          [10000, 256]
    G0<<<dim3(HID / 128, MT, 1), 128, SM_G01>>>(feature, W1p, nullptr, S1p, NN, HID, FIN);
    // G1: X1 = rna(relu(adj @ S1p + b1)) -> d_out  [10000, 256]
    G1<<<dim3(HID / 128, MT, 1), 128, SM_G01>>>(adj, S1p, b1, x1, NN, HID, NN);
    // G2: S2p = pi64(rna(X1 @ W2p))                [10000, 64]
    G2<<<dim3(1, MT, 1), 128, SM_G2>>>(x1, W2p, nullptr, S2p, NN, NCLS, HID);
    // G3: part[z] = adj @ S2p (split-K = 2)        [2][10000, 64]
    G3<<<dim3(1, MT, 2), 128, SM_G3>>>(adj, S2p, nullptr, part, NN, NCLS, NN);
    // combine + bias + log-softmax
    lsm_combine<<<(NN * 32 + 255) / 256, 256>>>(part, part + (long long)NN * NCLS, b2, lsm, NN);
}